// round 5
// baseline (speedup 1.0000x reference)
#include <cuda_runtime.h>
#include <stdint.h>
#include <math.h>

#define VIEWS 6
#define NPTS  20000
#define DDIM  512
#define ND    (NPTS*DDIM)
#define VND   (VIEWS*ND)
#define NTILES 157            // ceil(20000/128) row tiles -> stat partials per channel

// ---------------- scratch (device globals; no runtime allocation) ----------
__device__ __align__(16) float g_Y[3u*(unsigned)VND];   // raw Q,K,V linear outputs
__device__ float g_Spart [3*VIEWS*DDIM*NTILES];
__device__ float g_SQpart[3*VIEWS*DDIM*NTILES];
__device__ float g_S [3*VIEWS*DDIM];
__device__ float g_SQ[3*VIEWS*DDIM];
__device__ float g_Mpart[36*DDIM*40];
__device__ float g_M[36*DDIM];
__device__ float g_R[36];
__device__ float g_RS[VIEWS];
__device__ __align__(16) float g_av[DDIM];
__device__ __align__(16) float g_cv[DDIM];

// ---------------- tf32 helpers ---------------------------------------------
__device__ __forceinline__ uint32_t f2tf32(float x){
  uint32_t r; asm("cvt.rna.tf32.f32 %0, %1;" : "=r"(r) : "f"(x)); return r;
}
__device__ __forceinline__ void mma_tf32(float c[4], const uint32_t a[4], const uint32_t b[2]){
  asm volatile("mma.sync.aligned.m16n8k8.row.col.f32.tf32.tf32.f32 "
    "{%0,%1,%2,%3}, {%4,%5,%6,%7}, {%8,%9}, {%0,%1,%2,%3};\n"
    : "+f"(c[0]), "+f"(c[1]), "+f"(c[2]), "+f"(c[3])
    : "r"(a[0]), "r"(a[1]), "r"(a[2]), "r"(a[3]), "r"(b[0]), "r"(b[1]));
}

// ---------------- Kernel 1: QKV GEMMs + fused BN-stat partials --------------
// Y[n][c] = sum_k X[n][k]*W[c][k] + bias[c].  Tile 128x128, K-step 16.
// Epilogue also emits per-column sum / sumsq over this tile's valid rows.
__global__ __launch_bounds__(256) void gemm_qkv_kernel(
    const float* __restrict__ X,
    const float* __restrict__ W0, const float* __restrict__ W1, const float* __restrict__ W2,
    const float* __restrict__ b0, const float* __restrict__ b1, const float* __restrict__ b2)
{
  const int mv   = blockIdx.z;            // mat*6 + view
  const int mat  = mv / VIEWS;
  const int view = mv % VIEWS;
  const float* W    = (mat==0) ? W0 : ((mat==1) ? W1 : W2);
  const float* bias = (mat==0) ? b0 : ((mat==1) ? b1 : b2);
  const float* A = X + (size_t)view*ND;
  float* Y = g_Y + (size_t)mat*VND + (size_t)view*ND;

  const int n0  = blockIdx.y * 128;
  const int c0g = blockIdx.x * 128;

  __shared__ uint32_t sA[128*17];   // [row][k] padded
  __shared__ uint32_t sB[128*17];   // [n][k]   padded
  __shared__ float sSt[2][128];     // per-wM per-column sum
  __shared__ float sSq[2][128];     // per-wM per-column sumsq

  const int tid  = threadIdx.x;
  const int lane = tid & 31;
  const int warp = tid >> 5;
  const int wM = warp & 1, wN = warp >> 1;
  const int g  = lane >> 2, tig = lane & 3;

  float acc[4][4][4];
  #pragma unroll
  for (int a=0;a<4;a++)
    #pragma unroll
    for (int b=0;b<4;b++){ acc[a][b][0]=0.f; acc[a][b][1]=0.f; acc[a][b][2]=0.f; acc[a][b][3]=0.f; }

  float4 ra[2], rb[2];
  #pragma unroll
  for (int ch=0; ch<2; ch++){
    int f = ch*256 + tid;          // float4 index within 128x16 tile
    int row = f >> 2, q = f & 3;
    int grow = n0 + row;
    ra[ch] = (grow < NPTS) ? *(const float4*)(A + (size_t)grow*DDIM + q*4)
                           : make_float4(0.f,0.f,0.f,0.f);
    rb[ch] = *(const float4*)(W + (size_t)(c0g + row)*DDIM + q*4);
  }

  for (int kt = 0; kt < DDIM; kt += 16){
    __syncthreads();
    #pragma unroll
    for (int ch=0; ch<2; ch++){
      int f = ch*256 + tid;
      int row = f >> 2, q = f & 3;
      uint32_t* pa = &sA[row*17 + q*4];
      pa[0]=f2tf32(ra[ch].x); pa[1]=f2tf32(ra[ch].y); pa[2]=f2tf32(ra[ch].z); pa[3]=f2tf32(ra[ch].w);
      uint32_t* pb = &sB[row*17 + q*4];
      pb[0]=f2tf32(rb[ch].x); pb[1]=f2tf32(rb[ch].y); pb[2]=f2tf32(rb[ch].z); pb[3]=f2tf32(rb[ch].w);
    }
    __syncthreads();
    if (kt + 16 < DDIM){
      const int ktn = kt + 16;
      #pragma unroll
      for (int ch=0; ch<2; ch++){
        int f = ch*256 + tid;
        int row = f >> 2, q = f & 3;
        int grow = n0 + row;
        ra[ch] = (grow < NPTS) ? *(const float4*)(A + (size_t)grow*DDIM + ktn + q*4)
                               : make_float4(0.f,0.f,0.f,0.f);
        rb[ch] = *(const float4*)(W + (size_t)(c0g + row)*DDIM + ktn + q*4);
      }
    }
    #pragma unroll
    for (int kk=0; kk<2; kk++){
      const int k0 = kk*8;
      uint32_t af[4][4], bf[4][2];
      #pragma unroll
      for (int mt=0; mt<4; mt++){
        int mb = wM*64 + mt*16;
        af[mt][0] = sA[(mb+g  )*17 + k0 + tig];
        af[mt][1] = sA[(mb+g+8)*17 + k0 + tig];
        af[mt][2] = sA[(mb+g  )*17 + k0 + tig + 4];
        af[mt][3] = sA[(mb+g+8)*17 + k0 + tig + 4];
      }
      #pragma unroll
      for (int nt=0; nt<4; nt++){
        int nb = wN*32 + nt*8;
        bf[nt][0] = sB[(nb+g)*17 + k0 + tig];
        bf[nt][1] = sB[(nb+g)*17 + k0 + tig + 4];
      }
      #pragma unroll
      for (int mt=0; mt<4; mt++)
        #pragma unroll
        for (int nt=0; nt<4; nt++)
          mma_tf32(acc[mt][nt], af[mt], bf[nt]);
    }
  }

  // ---- epilogue: bias + store + fused per-column stat partials ----
  float s0[4], s1[4], q0[4], q1[4];   // per-nt column sums (col, col+1)
  #pragma unroll
  for (int nt=0;nt<4;nt++){ s0[nt]=0.f; s1[nt]=0.f; q0[nt]=0.f; q1[nt]=0.f; }

  #pragma unroll
  for (int nt=0; nt<4; nt++){
    int col = wN*32 + nt*8 + 2*tig;
    float bi0 = bias[c0g + col], bi1 = bias[c0g + col + 1];
    #pragma unroll
    for (int mt=0; mt<4; mt++){
      int row0 = n0 + wM*64 + mt*16 + g;
      if (row0 < NPTS){
        float vx = acc[mt][nt][0] + bi0, vy = acc[mt][nt][1] + bi1;
        float2 o; o.x = vx; o.y = vy;
        *(float2*)(Y + (size_t)row0*DDIM + c0g + col) = o;
        s0[nt] += vx; q0[nt] = fmaf(vx, vx, q0[nt]);
        s1[nt] += vy; q1[nt] = fmaf(vy, vy, q1[nt]);
      }
      int row1 = row0 + 8;
      if (row1 < NPTS){
        float vx = acc[mt][nt][2] + bi0, vy = acc[mt][nt][3] + bi1;
        float2 o; o.x = vx; o.y = vy;
        *(float2*)(Y + (size_t)row1*DDIM + c0g + col) = o;
        s0[nt] += vx; q0[nt] = fmaf(vx, vx, q0[nt]);
        s1[nt] += vy; q1[nt] = fmaf(vy, vy, q1[nt]);
      }
    }
  }
  // reduce over the 8 row-groups (g) within the warp: lanes tig + 4g
  #pragma unroll
  for (int nt=0; nt<4; nt++){
    #pragma unroll
    for (int mk=4; mk<32; mk<<=1){
      s0[nt] += __shfl_xor_sync(0xffffffffu, s0[nt], mk);
      s1[nt] += __shfl_xor_sync(0xffffffffu, s1[nt], mk);
      q0[nt] += __shfl_xor_sync(0xffffffffu, q0[nt], mk);
      q1[nt] += __shfl_xor_sync(0xffffffffu, q1[nt], mk);
    }
  }
  if (g == 0){
    #pragma unroll
    for (int nt=0; nt<4; nt++){
      int lc = wN*32 + nt*8 + 2*tig;
      sSt[wM][lc]   = s0[nt]; sSq[wM][lc]   = q0[nt];
      sSt[wM][lc+1] = s1[nt]; sSq[wM][lc+1] = q1[nt];
    }
  }
  __syncthreads();
  if (tid < 128){
    int cIdx = mv*DDIM + c0g + tid;
    g_Spart [(size_t)cIdx*NTILES + blockIdx.y] = sSt[0][tid] + sSt[1][tid];
    g_SQpart[(size_t)cIdx*NTILES + blockIdx.y] = sSq[0][tid] + sSq[1][tid];
  }
}

// ---------------- Kernel 2: parallel stat-partial reduction -----------------
// one thread per (mat,view,channel); fixed-order 157-step sum -> deterministic
__global__ __launch_bounds__(256) void sreduce_kernel(){
  int idx = blockIdx.x*256 + threadIdx.x;       // < 3*6*512 = 9216
  const float* ps = &g_Spart [(size_t)idx*NTILES];
  const float* pq = &g_SQpart[(size_t)idx*NTILES];
  float s=0.f, q=0.f;
  #pragma unroll 4
  for (int p=0;p<NTILES;p++){ s += ps[p]; q += pq[p]; }
  g_S[idx]=s; g_SQ[idx]=q;
}

// ---------------- Kernel 3: cross moments M_ijd partials --------------------
__global__ __launch_bounds__(256) void mpart_kernel(){
  const int dB  = blockIdx.x;   // 0..15
  const int nsp = blockIdx.y;   // 0..39
  const int tid = threadIdx.x;
  const int dl = tid & 31, ng = tid >> 5;
  const int d = dB*32 + dl;
  const float* Q = g_Y;
  const float* K = g_Y + (size_t)VND;
  float acc[36];
  #pragma unroll
  for (int p=0;p<36;p++) acc[p]=0.f;
  const int n1 = nsp*500 + 500;
  for (int n = nsp*500 + ng; n < n1; n += 8){
    float qv[6], kv[6];
    size_t base = (size_t)n*DDIM + d;
    #pragma unroll
    for (int i=0;i<6;i++){ qv[i] = Q[(size_t)i*ND + base]; kv[i] = K[(size_t)i*ND + base]; }
    #pragma unroll
    for (int i=0;i<6;i++)
      #pragma unroll
      for (int j=0;j<6;j++)
        acc[i*6+j] = fmaf(qv[i], kv[j], acc[i*6+j]);
  }
  __shared__ float red[8*36*32];   // 36 KB
  #pragma unroll
  for (int p=0;p<36;p++) red[(ng*36 + p)*32 + dl] = acc[p];
  __syncthreads();
  for (int idx = tid; idx < 36*32; idx += 256){
    int p = idx >> 5, d2 = idx & 31;
    float s=0.f;
    #pragma unroll
    for (int gg=0; gg<8; gg++) s += red[(gg*36 + p)*32 + d2];
    g_Mpart[(p*DDIM + dB*32 + d2)*40 + nsp] = s;
  }
}

__global__ __launch_bounds__(256) void mreduce_kernel(){
  int idx = blockIdx.x*256 + threadIdx.x;  // < 36*512
  float s=0.f;
  #pragma unroll 8
  for (int t=0;t<40;t++) s += g_Mpart[idx*40 + t];
  g_M[idx] = s;
}

// ---------------- Kernel 4: fused scalar stage ------------------------------
__global__ __launch_bounds__(256) void small_kernel(
    const float* __restrict__ gq, const float* __restrict__ bq,
    const float* __restrict__ gk, const float* __restrict__ bk,
    const float* __restrict__ gv, const float* __restrict__ bv)
{
  const int tid = threadIdx.x;
  __shared__ float sA[3][DDIM], sC[3][DDIM];
  __shared__ float rbuf[256];
  __shared__ float sFro[3][VIEWS];
  __shared__ float sP[36];

  // B: BN affine coefficients per channel (stats pooled over views)
  const float invM = 1.f/(float)(VIEWS*NPTS);
  for (int t = tid; t < 3*DDIM; t += 256){
    int m = t / DDIM, c = t - m*DDIM;
    float S=0.f, Q=0.f;
    #pragma unroll
    for (int v=0; v<VIEWS; v++){ S += g_S[(m*VIEWS+v)*DDIM + c]; Q += g_SQ[(m*VIEWS+v)*DDIM + c]; }
    float mean = S * invM;
    float var  = Q * invM - mean*mean;
    float r = rsqrtf(var + 1e-5f);
    const float* gam = (m==0)?gq:((m==1)?gk:gv);
    const float* bet = (m==0)?bq:((m==1)?bk:bv);
    float a = gam[c]*r;
    sA[m][c] = a;
    sC[m][c] = bet[c] - a*mean;
  }
  __syncthreads();

  // C: per-view Frobenius norms from moments
  for (int mv = 0; mv < 18; mv++){
    int m = mv/6, v = mv - (mv/6)*6;
    float p = 0.f;
    for (int c = tid; c < DDIM; c += 256){
      float a = sA[m][c], cc = sC[m][c];
      float S = g_S[(m*VIEWS+v)*DDIM + c], Q = g_SQ[(m*VIEWS+v)*DDIM + c];
      p += a*a*Q + 2.f*a*cc*S + (float)NPTS*cc*cc;
    }
    rbuf[tid] = p; __syncthreads();
    for (int s=128; s>0; s>>=1){ if (tid<s) rbuf[tid]+=rbuf[tid+s]; __syncthreads(); }
    if (tid==0) sFro[m][v] = sqrtf(fmaxf(rbuf[0],0.f)) + 1e-8f;
    __syncthreads();
  }

  // D: 6x6 Gram -> sigmoid
  for (int pp = 0; pp < 36; pp++){
    int i = pp/6, j = pp - (pp/6)*6;
    float acc = 0.f;
    for (int c = tid; c < DDIM; c += 256){
      float aq = sA[0][c], cq = sC[0][c];
      float ak = sA[1][c], ck = sC[1][c];
      float M  = g_M[pp*DDIM + c];
      float Sq = g_S[(0*VIEWS+i)*DDIM + c];
      float Sk = g_S[(1*VIEWS+j)*DDIM + c];
      acc += aq*ak*M + aq*ck*Sq + cq*ak*Sk + (float)NPTS*cq*ck;
    }
    rbuf[tid] = acc; __syncthreads();
    for (int s=128; s>0; s>>=1){ if (tid<s) rbuf[tid]+=rbuf[tid+s]; __syncthreads(); }
    if (tid==0){
      float G = rbuf[0] / (sFro[0][i]*sFro[1][j]);
      sP[pp] = 1.f/(1.f + expf(-G));
    }
    __syncthreads();
  }

  // E: doubly-stochastic projection (serial 6x6) + R,RS
  if (tid == 0){
    float P[6][6], A0[6][6], A1[6][6];
    for (int i=0;i<6;i++) for (int j=0;j<6;j++) P[i][j]=sP[i*6+j];
    for (int j=0;j<6;j++){                 // softmax over axis 0 (per column)
      float mx=-1e30f; for (int i=0;i<6;i++) mx=fmaxf(mx,P[i][j]);
      float s=0.f; for (int i=0;i<6;i++){ A0[i][j]=expf(P[i][j]-mx); s+=A0[i][j]; }
      for (int i=0;i<6;i++) A0[i][j]/=s;
    }
    for (int i=0;i<6;i++){                 // softmax over axis 1 (per row)
      float mx=-1e30f; for (int j=0;j<6;j++) mx=fmaxf(mx,P[i][j]);
      float s=0.f; for (int j=0;j<6;j++){ A1[i][j]=expf(P[i][j]-mx); s+=A1[i][j]; }
      for (int j=0;j<6;j++) A1[i][j]/=s;
    }
    for (int i=0;i<6;i++) for (int j=0;j<6;j++) P[i][j]=0.5f*(A0[i][j]+A1[i][j]);
    for (int it=0; it<10; it++){
      float rs[6];
      for (int i=0;i<6;i++){ rs[i]=0.f; for (int j=0;j<6;j++){ float v=fmaxf(P[i][j],0.f); P[i][j]=v; rs[i]+=v; } }
      for (int i=0;i<6;i++){ float d=(rs[i]-1.f)/6.f; for (int j=0;j<6;j++) P[i][j]-=d; }
      float cs[6];
      for (int j=0;j<6;j++){ cs[j]=0.f; for (int i=0;i<6;i++) cs[j]+=P[i][j]; }
      for (int j=0;j<6;j++){ float d=(cs[j]-1.f)/6.f; for (int i=0;i<6;i++) P[i][j]-=d; }
    }
    for (int j=0;j<6;j++){
      float rsum=0.f;
      for (int i=0;i<6;i++){ float r = P[i][j]/sFro[2][i]; g_R[i*6+j]=r; rsum+=r; }
      g_RS[j]=rsum;
    }
  }
  // F: publish V's BN affine coefficients
  for (int c = tid; c < DDIM; c += 256){ g_av[c]=sA[2][c]; g_cv[c]=sC[2][c]; }
}

// ---------------- Kernel 5: output mix --------------------------------------
__global__ __launch_bounds__(256) void out_kernel(float* __restrict__ out){
  __shared__ float sR[36], sRS[6];
  __shared__ float4 sav[128], scv[128];
  const int tid = threadIdx.x;
  if (tid < 36) sR[tid] = g_R[tid];
  if (tid < 6)  sRS[tid] = g_RS[tid];
  if (tid < 128){ sav[tid] = ((const float4*)g_av)[tid]; scv[tid] = ((const float4*)g_cv)[tid]; }
  __syncthreads();

  int t = blockIdx.x*256 + tid;          // float4 index within one view plane
  int c4 = t & 127;                       // 512/4 channels
  size_t off = (size_t)t*4;               // element offset within plane
  const float* V = g_Y + 2u*(unsigned)VND;
  float4 v[6];
  #pragma unroll
  for (int i=0;i<6;i++) v[i] = *(const float4*)(V + (size_t)i*ND + off);
  float4 av = sav[c4], cv = scv[c4];
  #pragma unroll
  for (int j=0;j<6;j++){
    float4 a; a.x=0.f; a.y=0.f; a.z=0.f; a.w=0.f;
    #pragma unroll
    for (int i=0;i<6;i++){
      float r = sR[i*6+j];
      a.x = fmaf(r, v[i].x, a.x); a.y = fmaf(r, v[i].y, a.y);
      a.z = fmaf(r, v[i].z, a.z); a.w = fmaf(r, v[i].w, a.w);
    }
    float rs = sRS[j];
    float4 o;
    o.x = fmaf(av.x, a.x, cv.x*rs); o.y = fmaf(av.y, a.y, cv.y*rs);
    o.z = fmaf(av.z, a.z, cv.z*rs); o.w = fmaf(av.w, a.w, cv.w*rs);
    *(float4*)(out + (size_t)j*ND + off) = o;
  }
}

// ---------------- launch -----------------------------------------------------
extern "C" void kernel_launch(void* const* d_in, const int* in_sizes, int n_in,
                              void* d_out, int out_size) {
  const float* X    = (const float*)d_in[0];
  const float* WQ_w = (const float*)d_in[1];
  const float* WQ_b = (const float*)d_in[2];
  const float* WK_w = (const float*)d_in[3];
  const float* WK_b = (const float*)d_in[4];
  const float* WV_w = (const float*)d_in[5];
  const float* WV_b = (const float*)d_in[6];
  const float* g_q  = (const float*)d_in[7];
  const float* b_q  = (const float*)d_in[8];
  const float* g_k  = (const float*)d_in[9];
  const float* b_k  = (const float*)d_in[10];
  const float* g_v  = (const float*)d_in[11];
  const float* b_v  = (const float*)d_in[12];
  float* out = (float*)d_out;

  dim3 gg(4, NTILES, 18);
  gemm_qkv_kernel<<<gg, 256>>>(X, WQ_w, WK_w, WV_w, WQ_b, WK_b, WV_b);

  sreduce_kernel<<<36, 256>>>();

  dim3 gm(16, 40);
  mpart_kernel<<<gm, 256>>>();

  mreduce_kernel<<<72, 256>>>();

  small_kernel<<<1, 256>>>(g_q, b_q, g_k, b_k, g_v, b_v);

  out_kernel<<<10000, 256>>>(out);
}

// round 8
// speedup vs baseline: 1.2592x; 1.2592x over previous
#include <cuda_runtime.h>
#include <stdint.h>
#include <math.h>

#define VIEWS 6
#define NPTS  20000
#define DDIM  512
#define ND    (NPTS*DDIM)
#define VND   (VIEWS*ND)
#define NTILES 157            // ceil(20000/128) row tiles -> stat partials per channel
#define STG_A 2048            // words per A smem stage (16 F * 32 lanes * 4 regs)
#define STG_B 2048            // words per B smem stage (32 F * 32 lanes * 2 regs)

// ---------------- scratch (device globals; no runtime allocation) ----------
__device__ __align__(16) float g_Y[3u*(unsigned)VND];   // raw Q,K,V linear outputs
__device__ float g_Spart [3*VIEWS*DDIM*NTILES];
__device__ float g_SQpart[3*VIEWS*DDIM*NTILES];
__device__ float g_S [3*VIEWS*DDIM];
__device__ float g_SQ[3*VIEWS*DDIM];
__device__ float g_Mpart[36*DDIM*40];
__device__ float g_M[36*DDIM];
__device__ float g_R[36];
__device__ float g_RS[VIEWS];
__device__ __align__(16) float g_av[DDIM];
__device__ __align__(16) float g_cv[DDIM];

// ---------------- tf32 helpers ---------------------------------------------
__device__ __forceinline__ uint32_t f2tf32(float x){
  uint32_t r; asm("cvt.rna.tf32.f32 %0, %1;" : "=r"(r) : "f"(x)); return r;
}
__device__ __forceinline__ void mma_tf32(float c[4], const uint32_t a[4], const uint32_t b[2]){
  asm volatile("mma.sync.aligned.m16n8k8.row.col.f32.tf32.tf32.f32 "
    "{%0,%1,%2,%3}, {%4,%5,%6,%7}, {%8,%9}, {%0,%1,%2,%3};\n"
    : "+f"(c[0]), "+f"(c[1]), "+f"(c[2]), "+f"(c[3])
    : "r"(a[0]), "r"(a[1]), "r"(a[2]), "r"(a[3]), "r"(b[0]), "r"(b[1]));
}

// ---------------- Kernel 1: QKV GEMMs + fused BN-stat partials --------------
// Y[n][c] = sum_k X[n][k]*W[c][k] + bias[c].  Tile 128x128, K-step 16.
// Fragment-packed double-buffered smem; one barrier per K-step.
// Epilogue emits per-column sum / sumsq over this tile's valid rows.
__global__ __launch_bounds__(256) void gemm_qkv_kernel(
    const float* __restrict__ X,
    const float* __restrict__ W0, const float* __restrict__ W1, const float* __restrict__ W2,
    const float* __restrict__ b0, const float* __restrict__ b1, const float* __restrict__ b2)
{
  const int mv   = blockIdx.z;            // mat*6 + view
  const int mat  = mv / VIEWS;
  const int view = mv % VIEWS;
  const float* W    = (mat==0) ? W0 : ((mat==1) ? W1 : W2);
  const float* bias = (mat==0) ? b0 : ((mat==1) ? b1 : b2);
  const float* A = X + (size_t)view*ND;
  float* Y = g_Y + (size_t)mat*VND + (size_t)view*ND;

  const int n0  = blockIdx.y * 128;
  const int c0g = blockIdx.x * 128;

  __shared__ uint32_t sA[2*STG_A];   // [stage][F=(m16*2+kk)][lane(swizzled)][reg0..3]
  __shared__ uint32_t sB[2*STG_B];   // [stage][F=(n8*2+kk)][lane(swizzled)][reg0..1]
  __shared__ float sSt[2][128];      // per-wM per-column sum
  __shared__ float sSq[2][128];      // per-wM per-column sumsq

  const int tid  = threadIdx.x;
  const int lane = tid & 31;
  const int warp = tid >> 5;
  const int wM = warp & 1, wN = warp >> 1;
  const int g  = lane >> 2, tig = lane & 3;
  // consumer-side swizzled lane (same bijection producers use)
  const int lp = (lane & ~3) | ((lane ^ (lane >> 3)) & 3);

  // per-thread staging coordinates (thread f covers float4 indices f and f+256)
  // of the 128x16 tile: row = f>>2, q = f&3 (k = 4q..4q+3)
  int rowc[2], regAc[2], FAc[2], regBc[2], FBc[2], swzc[2];
  #pragma unroll
  for (int ch=0; ch<2; ch++){
    int f = ch*256 + tid;
    int row = f >> 2, q = f & 3;
    int kk = q >> 1, thalf = q & 1;
    int gg = row & 7;
    rowc[ch] = row;
    regAc[ch] = ((row >> 3) & 1) + 2*thalf;
    FAc[ch]  = (row >> 4)*2 + kk;
    regBc[ch]= thalf;
    FBc[ch]  = (row >> 3)*2 + kk;
    swzc[ch] = (gg >> 1) & 3;
  }

  float acc[4][4][4];
  #pragma unroll
  for (int a=0;a<4;a++)
    #pragma unroll
    for (int b=0;b<4;b++){ acc[a][b][0]=0.f; acc[a][b][1]=0.f; acc[a][b][2]=0.f; acc[a][b][3]=0.f; }

  float4 ra[2], rb[2];
  // prologue LDG (kt = 0)
  #pragma unroll
  for (int ch=0; ch<2; ch++){
    int f = ch*256 + tid;
    int row = f >> 2, q = f & 3;
    int grow = n0 + row;
    ra[ch] = (grow < NPTS) ? *(const float4*)(A + (size_t)grow*DDIM + q*4)
                           : make_float4(0.f,0.f,0.f,0.f);
    rb[ch] = *(const float4*)(W + (size_t)(c0g + row)*DDIM + q*4);
  }

  int s = 0;
  for (int kt = 0; kt < DDIM; kt += 16){
    // ---- stage registers -> fragment-packed tf32 smem (stage s) ----
    #pragma unroll
    for (int ch=0; ch<2; ch++){
      const int gg = rowc[ch] & 7;
      uint32_t* baseA = sA + s*STG_A + FAc[ch]*128;
      uint32_t* baseB = sB + s*STG_B + FBc[ch]*64;
      float va[4] = {ra[ch].x, ra[ch].y, ra[ch].z, ra[ch].w};
      float vb[4] = {rb[ch].x, rb[ch].y, rb[ch].z, rb[ch].w};
      #pragma unroll
      for (int e=0;e<4;e++){
        int lpa = gg*4 + (e ^ swzc[ch]);
        baseA[lpa*4 + regAc[ch]] = f2tf32(va[e]);
        baseB[lpa*2 + regBc[ch]] = f2tf32(vb[e]);
      }
    }
    // ---- LDG next tile before the barrier (latency overlap) ----
    if (kt + 16 < DDIM){
      const int ktn = kt + 16;
      #pragma unroll
      for (int ch=0; ch<2; ch++){
        int f = ch*256 + tid;
        int row = f >> 2, q = f & 3;
        int grow = n0 + row;
        ra[ch] = (grow < NPTS) ? *(const float4*)(A + (size_t)grow*DDIM + ktn + q*4)
                               : make_float4(0.f,0.f,0.f,0.f);
        rb[ch] = *(const float4*)(W + (size_t)(c0g + row)*DDIM + ktn + q*4);
      }
    }
    __syncthreads();
    // ---- compute on stage s ----
    #pragma unroll
    for (int kk=0; kk<2; kk++){
      uint32_t af[4][4], bf[4][2];
      #pragma unroll
      for (int mt=0; mt<4; mt++){
        const uint4 v = *(const uint4*)&sA[s*STG_A + ((wM*4+mt)*2 + kk)*128 + lp*4];
        af[mt][0]=v.x; af[mt][1]=v.y; af[mt][2]=v.z; af[mt][3]=v.w;
      }
      #pragma unroll
      for (int nt=0; nt<4; nt++){
        const uint2 v = *(const uint2*)&sB[s*STG_B + ((wN*4+nt)*2 + kk)*64 + lp*2];
        bf[nt][0]=v.x; bf[nt][1]=v.y;
      }
      #pragma unroll
      for (int mt=0; mt<4; mt++)
        #pragma unroll
        for (int nt=0; nt<4; nt++)
          mma_tf32(acc[mt][nt], af[mt], bf[nt]);
    }
    s ^= 1;
  }

  // ---- epilogue: bias + store + fused per-column stat partials ----
  float s0[4], s1[4], q0[4], q1[4];
  #pragma unroll
  for (int nt=0;nt<4;nt++){ s0[nt]=0.f; s1[nt]=0.f; q0[nt]=0.f; q1[nt]=0.f; }

  #pragma unroll
  for (int nt=0; nt<4; nt++){
    int col = wN*32 + nt*8 + 2*tig;
    float bi0 = bias[c0g + col], bi1 = bias[c0g + col + 1];
    #pragma unroll
    for (int mt=0; mt<4; mt++){
      int row0 = n0 + wM*64 + mt*16 + g;
      if (row0 < NPTS){
        float vx = acc[mt][nt][0] + bi0, vy = acc[mt][nt][1] + bi1;
        float2 o; o.x = vx; o.y = vy;
        *(float2*)(Y + (size_t)row0*DDIM + c0g + col) = o;
        s0[nt] += vx; q0[nt] = fmaf(vx, vx, q0[nt]);
        s1[nt] += vy; q1[nt] = fmaf(vy, vy, q1[nt]);
      }
      int row1 = row0 + 8;
      if (row1 < NPTS){
        float vx = acc[mt][nt][2] + bi0, vy = acc[mt][nt][3] + bi1;
        float2 o; o.x = vx; o.y = vy;
        *(float2*)(Y + (size_t)row1*DDIM + c0g + col) = o;
        s0[nt] += vx; q0[nt] = fmaf(vx, vx, q0[nt]);
        s1[nt] += vy; q1[nt] = fmaf(vy, vy, q1[nt]);
      }
    }
  }
  #pragma unroll
  for (int nt=0; nt<4; nt++){
    #pragma unroll
    for (int mk=4; mk<32; mk<<=1){
      s0[nt] += __shfl_xor_sync(0xffffffffu, s0[nt], mk);
      s1[nt] += __shfl_xor_sync(0xffffffffu, s1[nt], mk);
      q0[nt] += __shfl_xor_sync(0xffffffffu, q0[nt], mk);
      q1[nt] += __shfl_xor_sync(0xffffffffu, q1[nt], mk);
    }
  }
  if (g == 0){
    #pragma unroll
    for (int nt=0; nt<4; nt++){
      int lc = wN*32 + nt*8 + 2*tig;
      sSt[wM][lc]   = s0[nt]; sSq[wM][lc]   = q0[nt];
      sSt[wM][lc+1] = s1[nt]; sSq[wM][lc+1] = q1[nt];
    }
  }
  __syncthreads();
  if (tid < 128){
    int cIdx = mv*DDIM + c0g + tid;
    g_Spart [(size_t)cIdx*NTILES + blockIdx.y] = sSt[0][tid] + sSt[1][tid];
    g_SQpart[(size_t)cIdx*NTILES + blockIdx.y] = sSq[0][tid] + sSq[1][tid];
  }
}

// ---------------- Kernel 2: parallel stat-partial reduction -----------------
__global__ __launch_bounds__(256) void sreduce_kernel(){
  int idx = blockIdx.x*256 + threadIdx.x;       // < 3*6*512 = 9216
  const float* ps = &g_Spart [(size_t)idx*NTILES];
  const float* pq = &g_SQpart[(size_t)idx*NTILES];
  float s=0.f, q=0.f;
  #pragma unroll 4
  for (int p=0;p<NTILES;p++){ s += ps[p]; q += pq[p]; }
  g_S[idx]=s; g_SQ[idx]=q;
}

// ---------------- Kernel 3: cross moments M_ijd partials --------------------
__global__ __launch_bounds__(256) void mpart_kernel(){
  const int dB  = blockIdx.x;   // 0..15
  const int nsp = blockIdx.y;   // 0..39
  const int tid = threadIdx.x;
  const int dl = tid & 31, ng = tid >> 5;
  const int d = dB*32 + dl;
  const float* Q = g_Y;
  const float* K = g_Y + (size_t)VND;
  float acc[36];
  #pragma unroll
  for (int p=0;p<36;p++) acc[p]=0.f;
  const int n1 = nsp*500 + 500;
  for (int n = nsp*500 + ng; n < n1; n += 8){
    float qv[6], kv[6];
    size_t base = (size_t)n*DDIM + d;
    #pragma unroll
    for (int i=0;i<6;i++){ qv[i] = Q[(size_t)i*ND + base]; kv[i] = K[(size_t)i*ND + base]; }
    #pragma unroll
    for (int i=0;i<6;i++)
      #pragma unroll
      for (int j=0;j<6;j++)
        acc[i*6+j] = fmaf(qv[i], kv[j], acc[i*6+j]);
  }
  __shared__ float red[8*36*32];   // 36 KB
  #pragma unroll
  for (int p=0;p<36;p++) red[(ng*36 + p)*32 + dl] = acc[p];
  __syncthreads();
  for (int idx = tid; idx < 36*32; idx += 256){
    int p = idx >> 5, d2 = idx & 31;
    float s=0.f;
    #pragma unroll
    for (int gg=0; gg<8; gg++) s += red[(gg*36 + p)*32 + d2];
    g_Mpart[(p*DDIM + dB*32 + d2)*40 + nsp] = s;
  }
}

__global__ __launch_bounds__(256) void mreduce_kernel(){
  int idx = blockIdx.x*256 + threadIdx.x;  // < 36*512
  float s=0.f;
  #pragma unroll 8
  for (int t=0;t<40;t++) s += g_Mpart[idx*40 + t];
  g_M[idx] = s;
}

// ---------------- Kernel 4: fused scalar stage ------------------------------
__global__ __launch_bounds__(256) void small_kernel(
    const float* __restrict__ gq, const float* __restrict__ bq,
    const float* __restrict__ gk, const float* __restrict__ bk,
    const float* __restrict__ gv, const float* __restrict__ bv)
{
  const int tid = threadIdx.x;
  __shared__ float sA[3][DDIM], sC[3][DDIM];
  __shared__ float rbuf[256];
  __shared__ float sFro[3][VIEWS];
  __shared__ float sP[36];

  // B: BN affine coefficients per channel (stats pooled over views)
  const float invM = 1.f/(float)(VIEWS*NPTS);
  for (int t = tid; t < 3*DDIM; t += 256){
    int m = t / DDIM, c = t - m*DDIM;
    float S=0.f, Q=0.f;
    #pragma unroll
    for (int v=0; v<VIEWS; v++){ S += g_S[(m*VIEWS+v)*DDIM + c]; Q += g_SQ[(m*VIEWS+v)*DDIM + c]; }
    float mean = S * invM;
    float var  = Q * invM - mean*mean;
    float r = rsqrtf(var + 1e-5f);
    const float* gam = (m==0)?gq:((m==1)?gk:gv);
    const float* bet = (m==0)?bq:((m==1)?bk:bv);
    float a = gam[c]*r;
    sA[m][c] = a;
    sC[m][c] = bet[c] - a*mean;
  }
  __syncthreads();

  // C: per-view Frobenius norms from moments
  for (int mv = 0; mv < 18; mv++){
    int m = mv/6, v = mv - (mv/6)*6;
    float p = 0.f;
    for (int c = tid; c < DDIM; c += 256){
      float a = sA[m][c], cc = sC[m][c];
      float S = g_S[(m*VIEWS+v)*DDIM + c], Q = g_SQ[(m*VIEWS+v)*DDIM + c];
      p += a*a*Q + 2.f*a*cc*S + (float)NPTS*cc*cc;
    }
    rbuf[tid] = p; __syncthreads();
    for (int s=128; s>0; s>>=1){ if (tid<s) rbuf[tid]+=rbuf[tid+s]; __syncthreads(); }
    if (tid==0) sFro[m][v] = sqrtf(fmaxf(rbuf[0],0.f)) + 1e-8f;
    __syncthreads();
  }

  // D: 6x6 Gram -> sigmoid
  for (int pp = 0; pp < 36; pp++){
    int i = pp/6, j = pp - (pp/6)*6;
    float acc = 0.f;
    for (int c = tid; c < DDIM; c += 256){
      float aq = sA[0][c], cq = sC[0][c];
      float ak = sA[1][c], ck = sC[1][c];
      float M  = g_M[pp*DDIM + c];
      float Sq = g_S[(0*VIEWS+i)*DDIM + c];
      float Sk = g_S[(1*VIEWS+j)*DDIM + c];
      acc += aq*ak*M + aq*ck*Sq + cq*ak*Sk + (float)NPTS*cq*ck;
    }
    rbuf[tid] = acc; __syncthreads();
    for (int s=128; s>0; s>>=1){ if (tid<s) rbuf[tid]+=rbuf[tid+s]; __syncthreads(); }
    if (tid==0){
      float G = rbuf[0] / (sFro[0][i]*sFro[1][j]);
      sP[pp] = 1.f/(1.f + expf(-G));
    }
    __syncthreads();
  }

  // E: doubly-stochastic projection (serial 6x6) + R,RS
  if (tid == 0){
    float P[6][6], A0[6][6], A1[6][6];
    for (int i=0;i<6;i++) for (int j=0;j<6;j++) P[i][j]=sP[i*6+j];
    for (int j=0;j<6;j++){                 // softmax over axis 0 (per column)
      float mx=-1e30f; for (int i=0;i<6;i++) mx=fmaxf(mx,P[i][j]);
      float s=0.f; for (int i=0;i<6;i++){ A0[i][j]=expf(P[i][j]-mx); s+=A0[i][j]; }
      for (int i=0;i<6;i++) A0[i][j]/=s;
    }
    for (int i=0;i<6;i++){                 // softmax over axis 1 (per row)
      float mx=-1e30f; for (int j=0;j<6;j++) mx=fmaxf(mx,P[i][j]);
      float s=0.f; for (int j=0;j<6;j++){ A1[i][j]=expf(P[i][j]-mx); s+=A1[i][j]; }
      for (int j=0;j<6;j++) A1[i][j]/=s;
    }
    for (int i=0;i<6;i++) for (int j=0;j<6;j++) P[i][j]=0.5f*(A0[i][j]+A1[i][j]);
    for (int it=0; it<10; it++){
      float rs[6];
      for (int i=0;i<6;i++){ rs[i]=0.f; for (int j=0;j<6;j++){ float v=fmaxf(P[i][j],0.f); P[i][j]=v; rs[i]+=v; } }
      for (int i=0;i<6;i++){ float d=(rs[i]-1.f)/6.f; for (int j=0;j<6;j++) P[i][j]-=d; }
      float cs[6];
      for (int j=0;j<6;j++){ cs[j]=0.f; for (int i=0;i<6;i++) cs[j]+=P[i][j]; }
      for (int j=0;j<6;j++){ float d=(cs[j]-1.f)/6.f; for (int i=0;i<6;i++) P[i][j]-=d; }
    }
    for (int j=0;j<6;j++){
      float rsum=0.f;
      for (int i=0;i<6;i++){ float r = P[i][j]/sFro[2][i]; g_R[i*6+j]=r; rsum+=r; }
      g_RS[j]=rsum;
    }
  }
  // F: publish V's BN affine coefficients
  for (int c = tid; c < DDIM; c += 256){ g_av[c]=sA[2][c]; g_cv[c]=sC[2][c]; }
}

// ---------------- Kernel 5: output mix --------------------------------------
__global__ __launch_bounds__(256) void out_kernel(float* __restrict__ out){
  __shared__ float sR[36], sRS[6];
  __shared__ float4 sav[128], scv[128];
  const int tid = threadIdx.x;
  if (tid < 36) sR[tid] = g_R[tid];
  if (tid < 6)  sRS[tid] = g_RS[tid];
  if (tid < 128){ sav[tid] = ((const float4*)g_av)[tid]; scv[tid] = ((const float4*)g_cv)[tid]; }
  __syncthreads();

  int t = blockIdx.x*256 + tid;          // float4 index within one view plane
  int c4 = t & 127;                       // 512/4 channels
  size_t off = (size_t)t*4;               // element offset within plane
  const float* V = g_Y + 2u*(unsigned)VND;
  float4 v[6];
  #pragma unroll
  for (int i=0;i<6;i++) v[i] = *(const float4*)(V + (size_t)i*ND + off);
  float4 av = sav[c4], cv = scv[c4];
  #pragma unroll
  for (int j=0;j<6;j++){
    float4 a; a.x=0.f; a.y=0.f; a.z=0.f; a.w=0.f;
    #pragma unroll
    for (int i=0;i<6;i++){
      float r = sR[i*6+j];
      a.x = fmaf(r, v[i].x, a.x); a.y = fmaf(r, v[i].y, a.y);
      a.z = fmaf(r, v[i].z, a.z); a.w = fmaf(r, v[i].w, a.w);
    }
    float rs = sRS[j];
    float4 o;
    o.x = fmaf(av.x, a.x, cv.x*rs); o.y = fmaf(av.y, a.y, cv.y*rs);
    o.z = fmaf(av.z, a.z, cv.z*rs); o.w = fmaf(av.w, a.w, cv.w*rs);
    *(float4*)(out + (size_t)j*ND + off) = o;
  }
}

// ---------------- launch -----------------------------------------------------
extern "C" void kernel_launch(void* const* d_in, const int* in_sizes, int n_in,
                              void* d_out, int out_size) {
  const float* X    = (const float*)d_in[0];
  const float* WQ_w = (const float*)d_in[1];
  const float* WQ_b = (const float*)d_in[2];
  const float* WK_w = (const float*)d_in[3];
  const float* WK_b = (const float*)d_in[4];
  const float* WV_w = (const float*)d_in[5];
  const float* WV_b = (const float*)d_in[6];
  const float* g_q  = (const float*)d_in[7];
  const float* b_q  = (const float*)d_in[8];
  const float* g_k  = (const float*)d_in[9];
  const float* b_k  = (const float*)d_in[10];
  const float* g_v  = (const float*)d_in[11];
  const float* b_v  = (const float*)d_in[12];
  float* out = (float*)d_out;

  dim3 gg(4, NTILES, 18);
  gemm_qkv_kernel<<<gg, 256>>>(X, WQ_w, WK_w, WV_w, WQ_b, WK_b, WV_b);

  sreduce_kernel<<<36, 256>>>();

  dim3 gm(16, 40);
  mpart_kernel<<<gm, 256>>>();

  mreduce_kernel<<<72, 256>>>();

  small_kernel<<<1, 256>>>(g_q, b_q, g_k, b_k, g_v, b_v);

  out_kernel<<<10000, 256>>>(out);
}